// round 4
// baseline (speedup 1.0000x reference)
#include <cuda_runtime.h>

// QuantumLayer: 4-qubit circuit, BATCH=1M.
// Analytic feature map (product state: amp_k = 0.25 * prod_w (c_w ± i s_w)),
// CNOTs = compile-time register permutations, RY gates as packed f32x2 math.
// 2 batch items per thread packed into f32x2 lanes (FFMA2 = 2x fp32 throughput).

typedef unsigned long long ull;

__device__ __forceinline__ ull pk(float a, float b) {
    ull r; asm("mov.b64 %0, {%1, %2};" : "=l"(r) : "f"(a), "f"(b)); return r;
}
__device__ __forceinline__ void upk(ull v, float& a, float& b) {
    asm("mov.b64 {%0, %1}, %2;" : "=f"(a), "=f"(b) : "l"(v));
}
__device__ __forceinline__ ull f2mul(ull a, ull b) {
    ull r; asm("mul.rn.f32x2 %0, %1, %2;" : "=l"(r) : "l"(a), "l"(b)); return r;
}
__device__ __forceinline__ ull f2add(ull a, ull b) {
    ull r; asm("add.rn.f32x2 %0, %1, %2;" : "=l"(r) : "l"(a), "l"(b)); return r;
}
__device__ __forceinline__ ull f2fma(ull a, ull b, ull c) {
    ull r; asm("fma.rn.f32x2 %0, %1, %2, %3;" : "=l"(r) : "l"(a), "l"(b), "l"(c)); return r;
}

#define F2_NEG1  0xBF800000BF800000ULL   // (-1, -1)
#define F2_QUART 0x3E8000003E800000ULL   // (0.25, 0.25)

// exact a - b (fma with -1 multiplier)
__device__ __forceinline__ ull f2sub(ull a, ull b) { return f2fma(b, (ull)F2_NEG1, a); }
__device__ __forceinline__ ull f2neg(ull a)        { return f2mul(a, (ull)F2_NEG1); }

// CNOT(control c, target t): for basis index k (wire 0 = MSB of 4 bits),
// swap amp[k] <-> amp[k|mt] for every k with control bit set, target bit clear.
#define CNOT(c_, t_)                                                          \
    {                                                                         \
        const int mc = 8 >> (c_), mt = 8 >> (t_);                             \
        _Pragma("unroll")                                                     \
        for (int k = 0; k < 16; ++k) {                                        \
            if ((k & mc) && !(k & mt)) {                                      \
                ull tr = ar[k]; ar[k] = ar[k | mt]; ar[k | mt] = tr;          \
                ull ti = ai[k]; ai[k] = ai[k | mt]; ai[k | mt] = ti;          \
            }                                                                 \
        }                                                                     \
    }

__global__ void __launch_bounds__(256)
quantum_layer_kernel(const float4* __restrict__ inp,
                     const float*  __restrict__ params,
                     float4* __restrict__ out, int npair, int B)
{
    int t = blockIdx.x * blockDim.x + threadIdx.x;
    if (t >= npair) return;

    // Two batch items per thread: lanes (a, b) of every f32x2.
    // Tail guard: if B is odd the last thread duplicates item A into lane B
    // and only writes lane A back.
    const int iA = 2 * t;
    const bool hasB = (iA + 1) < B;
    float4 inA = inp[iA];
    float4 inB = hasB ? inp[iA + 1] : inA;

    // ---- Prologue: all sincos up front (inputs: per-item; params: uniform).
    ull C[4], S[4];
    {
        float sa, ca, sb, cb;
        __sincosf(0.5f * inA.x, &sa, &ca); __sincosf(0.5f * inB.x, &sb, &cb);
        C[0] = pk(ca, cb); S[0] = pk(sa, sb);
        __sincosf(0.5f * inA.y, &sa, &ca); __sincosf(0.5f * inB.y, &sb, &cb);
        C[1] = pk(ca, cb); S[1] = pk(sa, sb);
        __sincosf(0.5f * inA.z, &sa, &ca); __sincosf(0.5f * inB.z, &sb, &cb);
        C[2] = pk(ca, cb); S[2] = pk(sa, sb);
        __sincosf(0.5f * inA.w, &sa, &ca); __sincosf(0.5f * inB.w, &sb, &cb);
        C[3] = pk(ca, cb); S[3] = pk(sa, sb);
    }
    ull PC[8], PS[8], PNS[8];   // variational RY half-angle cos/sin (uniform)
#pragma unroll
    for (int g = 0; g < 8; ++g) {
        float s, c;
        __sincosf(0.5f * __ldg(&params[g]), &s, &c);
        PC[g] = pk(c, c); PS[g] = pk(s, s); PNS[g] = pk(-s, -s);
    }

    // ---- Feature map (analytic): amp_k = 0.25 * prod_w (c_w + i*sigma_w*s_w),
    //      sigma_w = +1 if bit_w(k)==1 else -1. Tensor-product expansion.
    ull ar[16], ai[16];
    {
        ull x = f2mul((ull)F2_QUART, C[0]);
        ull y = f2mul((ull)F2_QUART, S[0]);
        ar[0] = x; ai[0] = f2neg(y);   // bit0 of wire0 -> (c - i s)
        ar[1] = x; ai[1] = y;          // bit1 -> (c + i s)
    }
#pragma unroll
    for (int w = 1; w < 4; ++w) {
        const int n = 1 << w;
        ull cw = C[w], sw = S[w], nsw = f2neg(sw);
#pragma unroll
        for (int j = n - 1; j >= 0; --j) {
            ull pr = ar[j], pi = ai[j];
            ull prc = f2mul(pr, cw), pic = f2mul(pi, cw);
            // child bit=0: (c - i s): re = pr*c + pi*s, im = pi*c - pr*s
            ar[2 * j]     = f2fma(pi, sw,  prc);
            ai[2 * j]     = f2fma(pr, nsw, pic);
            // child bit=1: (c + i s): re = pr*c - pi*s, im = pi*c + pr*s
            ar[2 * j + 1] = f2fma(pi, nsw, prc);
            ai[2 * j + 1] = f2fma(pr, sw,  pic);
        }
    }

    // Feature-map CNOT chain
    CNOT(0, 1); CNOT(1, 2); CNOT(2, 3);

    // ---- Variational layers: RY(params[layer,w]) per wire, then CNOT ring.
#pragma unroll
    for (int layer = 0; layer < 2; ++layer) {
#pragma unroll
        for (int w = 0; w < 4; ++w) {
            const int g = layer * 4 + w;
            ull Cp = PC[g], Sp = PS[g], nSp = PNS[g];
            const int m = 8 >> w;
#pragma unroll
            for (int k = 0; k < 16; ++k) {
                if (!(k & m)) {
                    const int k1 = k | m;
                    // new0 = c*a0 - s*a1 ; new1 = s*a0 + c*a1  (re and im)
                    ull a0 = ar[k], a1 = ar[k1];
                    ull ca0 = f2mul(Cp, a0), ca1 = f2mul(Cp, a1);
                    ar[k]  = f2fma(nSp, a1, ca0);
                    ar[k1] = f2fma(Sp,  a0, ca1);
                    ull b0 = ai[k], b1 = ai[k1];
                    ull cb0 = f2mul(Cp, b0), cb1 = f2mul(Cp, b1);
                    ai[k]  = f2fma(nSp, b1, cb0);
                    ai[k1] = f2fma(Sp,  b0, cb1);
                }
            }
        }
        CNOT(0, 1); CNOT(1, 2); CNOT(2, 3); CNOT(3, 0);
    }

    // ---- Readout: probs then signed butterfly sums (PauliZ per wire).
    ull p[16];
#pragma unroll
    for (int k = 0; k < 16; ++k)
        p[k] = f2fma(ar[k], ar[k], f2mul(ai[k], ai[k]));

    ull u[8], v[8];
#pragma unroll
    for (int j = 0; j < 8; ++j) {
        u[j] = f2add(p[2 * j], p[2 * j + 1]);
        v[j] = f2sub(p[2 * j], p[2 * j + 1]);
    }
    // wire 3 (LSB): sum of v
    ull o3 = f2add(f2add(f2add(v[0], v[1]), f2add(v[2], v[3])),
                   f2add(f2add(v[4], v[5]), f2add(v[6], v[7])));
    ull a2[4], b2[4];
#pragma unroll
    for (int m = 0; m < 4; ++m) {
        a2[m] = f2add(u[2 * m], u[2 * m + 1]);
        b2[m] = f2sub(u[2 * m], u[2 * m + 1]);
    }
    ull o2 = f2add(f2add(b2[0], b2[1]), f2add(b2[2], b2[3]));
    ull A0 = f2add(a2[0], a2[1]), B0 = f2sub(a2[0], a2[1]);
    ull A1 = f2add(a2[2], a2[3]), B1 = f2sub(a2[2], a2[3]);
    ull o1 = f2add(B0, B1);
    ull o0 = f2sub(A0, A1);

    float o0a, o0b, o1a, o1b, o2a, o2b, o3a, o3b;
    upk(o0, o0a, o0b); upk(o1, o1a, o1b);
    upk(o2, o2a, o2b); upk(o3, o3a, o3b);

    out[iA] = make_float4(o0a, o1a, o2a, o3a);
    if (hasB) out[iA + 1] = make_float4(o0b, o1b, o2b, o3b);
}

extern "C" void kernel_launch(void* const* d_in, const int* in_sizes, int n_in,
                              void* d_out, int out_size)
{
    const float* inputs = (const float*)d_in[0];   // (B, 4) float32
    const float* params = (const float*)d_in[1];   // (2, 4) float32
    float* outp = (float*)d_out;                   // (B, 4) float32

    int B = in_sizes[0] / 4;
    int npair = (B + 1) / 2;
    int threads = 256;
    int blocks = (npair + threads - 1) / threads;

    quantum_layer_kernel<<<blocks, threads>>>((const float4*)inputs, params,
                                              (float4*)outp, npair, B);
}

// round 6
// speedup vs baseline: 1.0802x; 1.0802x over previous
#include <cuda_runtime.h>

// QuantumLayer via Pauli-transfer closed form.
//
// After H+RZ(theta_w), each wire's 1-qubit state has <Z>=0, <X>=cos(theta),
// <Y>=sin(theta). Everything downstream (feature CNOT chain + variational
// circuit) is one fixed REAL orthogonal operator U (depends only on params).
// With O_j = U^T Z_j U (real symmetric), the outputs are exactly
//     o_j = sum_t W_j[t] * prod_w b_w(t_w),  b_w = (1, cos t_w, sin t_w),
// over Pauli strings t in {I,X,Y}^4 with an EVEN number of Y's (41 terms);
// W_j[t] = tr(O_j P_t)/16 computed once per launch by a tiny setup kernel.
//
// Main kernel: 2 batch items per thread packed into f32x2 lanes.
// ~46 packed muls (monomials) + 164 packed fmas (weights from shared memory).

typedef unsigned long long ull;

__device__ __forceinline__ ull pk(float a, float b) {
    ull r; asm("mov.b64 %0, {%1, %2};" : "=l"(r) : "f"(a), "f"(b)); return r;
}
__device__ __forceinline__ void upk(ull v, float& a, float& b) {
    asm("mov.b64 {%0, %1}, %2;" : "=f"(a), "=f"(b) : "l"(v));
}
__device__ __forceinline__ ull f2mul(ull a, ull b) {
    ull r; asm("mul.rn.f32x2 %0, %1, %2;" : "=l"(r) : "l"(a), "l"(b)); return r;
}
__device__ __forceinline__ ull f2fma(ull a, ull b, ull c) {
    ull r; asm("fma.rn.f32x2 %0, %1, %2, %3;" : "=l"(r) : "l"(a), "l"(b), "l"(c)); return r;
}

#define F2_ONE 0x3F8000003F800000ULL   // (1.0f, 1.0f)

// Weights: [j*41 + tIdx], j = output wire, tIdx = even-Y string index
// (lexicographic over t0*27+t1*9+t2*3+t3, wire0 = MSB).
__device__ float g_W[164];

// ---------------------------------------------------------------------------
// Setup kernel: grid = 164 blocks (one per (j, tIdx)), 32 threads each.
// Each block simulates U's 16 columns (threads 0..15), then computes
// W = sign * (1/16) * sum_l v(l) * O_j[l^f, l].
// ---------------------------------------------------------------------------

#define CNOTF(c_, t_)                                                         \
    {                                                                         \
        const int mc = 8 >> (c_), mt = 8 >> (t_);                             \
        _Pragma("unroll")                                                     \
        for (int k = 0; k < 16; ++k)                                          \
            if ((k & mc) && !(k & mt)) {                                      \
                float tmp = st[k]; st[k] = st[k | mt]; st[k | mt] = tmp;      \
            }                                                                 \
    }

__global__ void setup_weights(const float* __restrict__ params)
{
    __shared__ float sU[16][17];   // sU[m][k] = (U e_k)[m]
    const int tid = threadIdx.x;

    float pc[8], ps[8];
#pragma unroll
    for (int g = 0; g < 8; ++g) {
        float th = 0.5f * params[g];
        ps[g] = sinf(th); pc[g] = cosf(th);
    }

    if (tid < 16) {
        float st[16];
#pragma unroll
        for (int i = 0; i < 16; ++i) st[i] = 0.0f;
        st[tid] = 1.0f;
        // feature-map CNOT chain
        CNOTF(0, 1); CNOTF(1, 2); CNOTF(2, 3);
        // variational layers
#pragma unroll
        for (int layer = 0; layer < 2; ++layer) {
#pragma unroll
            for (int w = 0; w < 4; ++w) {
                const float c = pc[layer * 4 + w], s = ps[layer * 4 + w];
                const int m = 8 >> w;
#pragma unroll
                for (int k = 0; k < 16; ++k)
                    if (!(k & m)) {
                        const int k1 = k | m;
                        float a0 = st[k], a1 = st[k1];
                        st[k]  = c * a0 - s * a1;
                        st[k1] = s * a0 + c * a1;
                    }
            }
            CNOTF(0, 1); CNOTF(1, 2); CNOTF(2, 3); CNOTF(3, 0);
        }
#pragma unroll
        for (int m = 0; m < 16; ++m) sU[m][tid] = st[m];
    }
    __syncthreads();

    // Decode (j, tIdx) -> Pauli string encoding
    const int b = blockIdx.x;
    const int j = b / 41, tIdx = b % 41;
    int enc = 0, cnt = -1;
    for (int e = 0; e < 81; ++e) {
        int ny = ((e / 27) == 2) + (((e / 9) % 3) == 2) +
                 (((e / 3) % 3) == 2) + ((e % 3) == 2);
        if (!(ny & 1)) { if (++cnt == tIdx) { enc = e; break; } }
    }
    const int t0 = enc / 27, t1 = (enc / 9) % 3, t2 = (enc / 3) % 3, t3 = enc % 3;
    const int ny = (t0 == 2) + (t1 == 2) + (t2 == 2) + (t3 == 2);
    const int f  = (t0 ? 8 : 0) | (t1 ? 4 : 0) | (t2 ? 2 : 0) | (t3 ? 1 : 0);
    const float sign0 = (ny == 2) ? -1.0f : 1.0f;   // i^nY for even nY

    float part = 0.0f;
    if (tid < 16) {
        const int l = tid, lf = l ^ f;
        float vl = 1.0f;                            // prod over Y wires of (1 - 2*bit)
        if (t0 == 2 && (l & 8)) vl = -vl;
        if (t1 == 2 && (l & 4)) vl = -vl;
        if (t2 == 2 && (l & 2)) vl = -vl;
        if (t3 == 2 && (l & 1)) vl = -vl;
        float oacc = 0.0f;                          // O_j[lf, l]
#pragma unroll
        for (int m = 0; m < 16; ++m) {
            float z = ((m >> (3 - j)) & 1) ? -1.0f : 1.0f;
            oacc += z * sU[m][lf] * sU[m][l];
        }
        part = vl * oacc;
    }
#pragma unroll
    for (int off = 16; off; off >>= 1)
        part += __shfl_down_sync(0xffffffff, part, off);
    if (tid == 0) g_W[b] = sign0 * part * (1.0f / 16.0f);
}

// ---------------------------------------------------------------------------
// Main kernel: per thread, 2 batch items in f32x2 lanes.
// ---------------------------------------------------------------------------

__global__ void __launch_bounds__(256)
quantum_layer_kernel(const float4* __restrict__ inp,
                     float4* __restrict__ out, int npair, int B)
{
    __shared__ ull sW[164];   // weights duplicated into both lanes
    for (int i = threadIdx.x; i < 164; i += 256) {
        float w = g_W[i];
        sW[i] = pk(w, w);
    }
    __syncthreads();

    const int t = blockIdx.x * blockDim.x + threadIdx.x;
    if (t >= npair) return;

    const int iA = 2 * t;
    const bool hasB = (iA + 1) < B;
    float4 inA = inp[iA];
    float4 inB = hasB ? inp[iA + 1] : inA;

    // Full-angle cos/sin per wire, packed (lane a = item A, lane b = item B).
    ull Cw[4], Sw[4];
    {
        float sa, ca, sb, cb;
        __sincosf(inA.x, &sa, &ca); __sincosf(inB.x, &sb, &cb);
        Cw[0] = pk(ca, cb); Sw[0] = pk(sa, sb);
        __sincosf(inA.y, &sa, &ca); __sincosf(inB.y, &sb, &cb);
        Cw[1] = pk(ca, cb); Sw[1] = pk(sa, sb);
        __sincosf(inA.z, &sa, &ca); __sincosf(inB.z, &sb, &cb);
        Cw[2] = pk(ca, cb); Sw[2] = pk(sa, sb);
        __sincosf(inA.w, &sa, &ca); __sincosf(inB.w, &sb, &cb);
        Cw[3] = pk(ca, cb); Sw[3] = pk(sa, sb);
    }

    // Monomials over wires 0,1: m01[t0*3+t1], with aliases for identity factors.
    ull m01[9];
    m01[0] = F2_ONE;
    m01[1] = Cw[1];              m01[2] = Sw[1];
    m01[3] = Cw[0];              m01[6] = Sw[0];
    m01[4] = f2mul(Cw[0], Cw[1]); m01[5] = f2mul(Cw[0], Sw[1]);
    m01[7] = f2mul(Sw[0], Cw[1]); m01[8] = f2mul(Sw[0], Sw[1]);

    ull o0 = 0, o1 = 0, o2 = 0, o3 = 0;
    int idx = 0;
#pragma unroll
    for (int t0 = 0; t0 < 3; ++t0)
#pragma unroll
    for (int t1 = 0; t1 < 3; ++t1) {
        const int p01 = t0 * 3 + t1;
#pragma unroll
        for (int t2 = 0; t2 < 3; ++t2) {
            ull pre;
            bool preOne = false;
            if (t2 == 0)       { pre = m01[p01]; preOne = (p01 == 0); }
            else if (p01 == 0) { pre = (t2 == 1) ? Cw[2] : Sw[2]; }
            else               { pre = f2mul(m01[p01], (t2 == 1) ? Cw[2] : Sw[2]); }
#pragma unroll
            for (int t3 = 0; t3 < 3; ++t3) {
                const int ny = (t0 == 2) + (t1 == 2) + (t2 == 2) + (t3 == 2);
                if (ny & 1) continue;   // odd-Y strings have zero weight
                ull m;
                if (t3 == 0)      m = pre;
                else if (preOne)  m = (t3 == 1) ? Cw[3] : Sw[3];
                else              m = f2mul(pre, (t3 == 1) ? Cw[3] : Sw[3]);
                o0 = f2fma(m, sW[idx],       o0);
                o1 = f2fma(m, sW[41 + idx],  o1);
                o2 = f2fma(m, sW[82 + idx],  o2);
                o3 = f2fma(m, sW[123 + idx], o3);
                ++idx;
            }
        }
    }

    float o0a, o0b, o1a, o1b, o2a, o2b, o3a, o3b;
    upk(o0, o0a, o0b); upk(o1, o1a, o1b);
    upk(o2, o2a, o2b); upk(o3, o3a, o3b);

    out[iA] = make_float4(o0a, o1a, o2a, o3a);
    if (hasB) out[iA + 1] = make_float4(o0b, o1b, o2b, o3b);
}

extern "C" void kernel_launch(void* const* d_in, const int* in_sizes, int n_in,
                              void* d_out, int out_size)
{
    const float* inputs = (const float*)d_in[0];   // (B, 4) float32
    const float* params = (const float*)d_in[1];   // (2, 4) float32
    float* outp = (float*)d_out;                   // (B, 4) float32

    int B = in_sizes[0] / 4;
    int npair = (B + 1) / 2;
    int threads = 256;
    int blocks = (npair + threads - 1) / threads;

    setup_weights<<<164, 32>>>(params);
    quantum_layer_kernel<<<blocks, threads>>>((const float4*)inputs,
                                              (float4*)outp, npair, B);
}